// round 5
// baseline (speedup 1.0000x reference)
#include <cuda_runtime.h>
#include <math.h>

#define KLBL 32
#define MAXB 16
#define MAXHW 409600
#define FULLMASK 0xffffffffu
#define DELTA_V 0.5f
#define TWO_DELTA_D 3.0f
#define QSCALE 262144.0f           // 2^18 fixed-point scale
#define INVQ   (1.0f / 262144.0f)

// ---------------- scratch (device globals: no allocation allowed) ----------------
__device__ float g_sum[MAXB][KLBL][4];    // kernel-region segment sums
__device__ float g_cnt[MAXB][KLBL];       // per-label pixel count (tm-applied)
__device__ float g_cntk[MAXB][KLBL];      // per-label kernel-region count
__device__ float g_lagg[MAXB];            // accumulated l_agg per batch
__device__ unsigned char g_lab[(size_t)MAXB * MAXHW];  // tm-applied labels (6.5MB)

// ---------------- helpers ----------------
__device__ __forceinline__ int redux_add_s32(unsigned mask, int v) {
    int r;
    asm volatile("redux.sync.add.s32 %0, %1, %2;" : "=r"(r) : "r"(v), "r"(mask));
    return r;
}
// 32-byte load with evict-last L2 policy (requires .v4.b64 on sm_100 base)
__device__ __forceinline__ void ldg_el_v8(const void* p, unsigned long long r[4]) {
    asm("ld.global.nc.L2::evict_last.v4.b64 {%0,%1,%2,%3}, [%4];"
        : "=l"(r[0]), "=l"(r[1]), "=l"(r[2]), "=l"(r[3]) : "l"(p));
}
// 32-byte streaming (evict-first) load
__device__ __forceinline__ void ldcs_v8(const void* p, unsigned long long r[4]) {
    asm("ld.global.cs.v4.b64 {%0,%1,%2,%3}, [%4];"
        : "=l"(r[0]), "=l"(r[1]), "=l"(r[2]), "=l"(r[3]) : "l"(p));
}
__device__ __forceinline__ float lo_f(unsigned long long v) {
    return __uint_as_float((unsigned)(v & 0xffffffffull));
}
__device__ __forceinline__ float hi_f(unsigned long long v) {
    return __uint_as_float((unsigned)(v >> 32));
}
__device__ __forceinline__ float sqrt_approx(float x) {
    float r;
    asm("sqrt.approx.f32 %0, %1;" : "=f"(r) : "f"(x));
    return r;
}
__device__ __forceinline__ int f2i_rni(float x) {
    int r;
    asm("cvt.rni.s32.f32 %0, %1;" : "=r"(r) : "f"(x));
    return r;
}

// ---------------- kernel 0: zero accumulators + output ----------------
__global__ void k_zero(int B, float* out) {
    int t = blockIdx.x * blockDim.x + threadIdx.x;
    int n1 = B * KLBL;
    if (t < n1 * 4) ((float*)g_sum)[t] = 0.f;
    if (t < n1) { ((float*)g_cnt)[t] = 0.f; ((float*)g_cntk)[t] = 0.f; }
    if (t < B) g_lagg[t] = 0.f;
    if (t == 0) out[0] = 0.f;
}

// ---------------- kernel 1: segment sums / counts / label bytes ----------------
// 8 pixels per thread-iteration via 32-byte loads. Per-pixel scatter into 32
// bins: match_any gives disjoint group masks; redux.sync.add.s32 on fixed-point
// quantized values produces each group's sum in ONE instruction. Group leader
// does non-atomic RMW into warp-private int smem bins.
__global__ void __launch_bounds__(256) k_pass1(
    const float* __restrict__ emb, const int* __restrict__ inst,
    const float* __restrict__ ker, const float* __restrict__ tmk,
    int HW, int nv8)
{
    int b = blockIdx.y;
    const float* e0 = emb + ((size_t)b * 4 + 0) * HW;
    const float* e1 = emb + ((size_t)b * 4 + 1) * HW;
    const float* e2 = emb + ((size_t)b * 4 + 2) * HW;
    const float* e3 = emb + ((size_t)b * 4 + 3) * HW;
    const int*   ip = inst + (size_t)b * HW;
    const float* kp = ker  + (size_t)b * HW;
    const float* tp = tmk  + (size_t)b * HW;
    unsigned long long* lp = (unsigned long long*)(g_lab + (size_t)b * HW);

    __shared__ int s_bins[8][KLBL][7];   // per-warp: 4 qsum, cnt, cntk (+pad)
    for (int i = threadIdx.x; i < 8 * KLBL * 7; i += blockDim.x)
        ((int*)s_bins)[i] = 0;
    __syncthreads();

    int lane = threadIdx.x & 31;
    unsigned lt = (1u << lane) - 1u;
    int (*mybins)[7] = s_bins[threadIdx.x >> 5];

    for (int v = blockIdx.x * blockDim.x + threadIdx.x; v < nv8;
         v += gridDim.x * blockDim.x) {
        unsigned long long r0[4], r1[4], r2[4], r3[4], ri[4], rk[4], rt[4];
        ldg_el_v8(e0 + (size_t)v * 8, r0);
        ldg_el_v8(e1 + (size_t)v * 8, r1);
        ldg_el_v8(e2 + (size_t)v * 8, r2);
        ldg_el_v8(e3 + (size_t)v * 8, r3);
        ldcs_v8(ip + (size_t)v * 8, ri);
        ldcs_v8(kp + (size_t)v * 8, rk);
        ldcs_v8(tp + (size_t)v * 8, rt);

        unsigned long long packed = 0ull;
        #pragma unroll
        for (int j = 0; j < 8; j++) {
            int h = j >> 1;
            bool odd = j & 1;
            float x0 = odd ? hi_f(r0[h]) : lo_f(r0[h]);
            float x1 = odd ? hi_f(r1[h]) : lo_f(r1[h]);
            float x2 = odd ? hi_f(r2[h]) : lo_f(r2[h]);
            float x3 = odd ? hi_f(r3[h]) : lo_f(r3[h]);
            int   Li = odd ? (int)(ri[h] >> 32) : (int)(ri[h] & 0xffffffffull);
            float kvf = odd ? hi_f(rk[h]) : lo_f(rk[h]);
            float tvf = odd ? hi_f(rt[h]) : lo_f(rt[h]);

            int L = (tvf > 0.5f) ? Li : 0;
            bool kf = (kvf > 0.5f);
            packed |= ((unsigned long long)(L & 0xff)) << (8 * j);

            unsigned m  = __match_any_sync(FULLMASK, L);
            unsigned kb = __ballot_sync(FULLMASK, kf);

            int q0 = kf ? f2i_rni(x0 * QSCALE) : 0;
            int q1 = kf ? f2i_rni(x1 * QSCALE) : 0;
            int q2 = kf ? f2i_rni(x2 * QSCALE) : 0;
            int q3 = kf ? f2i_rni(x3 * QSCALE) : 0;
            int s0 = redux_add_s32(m, q0);
            int s1 = redux_add_s32(m, q1);
            int s2 = redux_add_s32(m, q2);
            int s3 = redux_add_s32(m, q3);

            if (L > 0 && (m & lt) == 0u) {   // group leader
                int* bp = mybins[L];
                bp[0] += s0; bp[1] += s1; bp[2] += s2; bp[3] += s3;
                bp[4] += __popc(m);
                bp[5] += __popc(m & kb);
            }
        }
        lp[v] = packed;
    }
    __syncthreads();

    // cross-warp reduce, dequantize, one global atomic per (label, component)
    for (int i = threadIdx.x; i < KLBL * 6; i += blockDim.x) {
        int k = i / 6, comp = i % 6;
        int s = 0;
        #pragma unroll
        for (int w = 0; w < 8; w++) s += s_bins[w][k][comp];
        if (s != 0) {
            if (comp < 4)       atomicAdd(&g_sum[b][k][comp], (float)s * INVQ);
            else if (comp == 4) atomicAdd(&g_cnt[b][k], (float)s);
            else                atomicAdd(&g_cntk[b][k], (float)s);
        }
    }
}

// ---------------- kernel 2: l_agg (means recomputed locally, weighted reduce) ----------------
__global__ void __launch_bounds__(256) k_pass2(
    const float* __restrict__ emb, const float* __restrict__ maxd,
    int HW, int nvec)
{
    int b = blockIdx.y;
    __shared__ float4 s_mean[KLBL];
    __shared__ float  s_sc[KLBL];
    __shared__ float  s_w[KLBL];
    __shared__ float  s_red[8];
    if (threadIdx.x < KLBL) {
        int k = threadIdx.x;
        float inv = 1.f / fmaxf(g_cntk[b][k], 1.f);
        float4 m;
        m.x = g_sum[b][k][0] * inv; m.y = g_sum[b][k][1] * inv;
        m.z = g_sum[b][k][2] * inv; m.w = g_sum[b][k][3] * inv;
        if (k == 0) { m.x = m.y = m.z = m.w = 0.f; }
        s_mean[k] = m;
        s_sc[k] = expf(maxd[b * KLBL + k]);
        s_w[k]  = 1.f / (31.f * fmaxf(g_cnt[b][k], 1.f));
    }
    __syncthreads();

    const float4* e0 = (const float4*)(emb + ((size_t)b * 4 + 0) * HW);
    const float4* e1 = (const float4*)(emb + ((size_t)b * 4 + 1) * HW);
    const float4* e2 = (const float4*)(emb + ((size_t)b * 4 + 2) * HW);
    const float4* e3 = (const float4*)(emb + ((size_t)b * 4 + 3) * HW);
    const unsigned int* lp = (const unsigned int*)(g_lab + (size_t)b * HW);

    float acc = 0.f;
    for (int v = blockIdx.x * blockDim.x + threadIdx.x; v < nvec;
         v += gridDim.x * blockDim.x) {
        unsigned lw = __ldg(lp + v);
        float4 a = __ldg(e0 + v), b4 = __ldg(e1 + v);
        float4 c = __ldg(e2 + v), d4 = __ldg(e3 + v);
        float p0[4] = {a.x, a.y, a.z, a.w};
        float p1[4] = {b4.x, b4.y, b4.z, b4.w};
        float p2[4] = {c.x, c.y, c.z, c.w};
        float p3[4] = {d4.x, d4.y, d4.z, d4.w};
        #pragma unroll
        for (int j = 0; j < 4; j++) {
            int L = (lw >> (8 * j)) & 0xff;
            if (L) {
                float4 m = s_mean[L];
                float dx = p0[j] - m.x, dy = p1[j] - m.y;
                float dz = p2[j] - m.z, dw = p3[j] - m.w;
                float d2 = fmaf(dx, dx, fmaf(dy, dy, fmaf(dz, dz, dw * dw)));
                float dist = sqrt_approx(d2);
                float y = fmaxf(fmaf(s_sc[L], dist, -DELTA_V), 0.f);
                acc = fmaf(__logf(fmaf(y, y, 1.f)), s_w[L], acc);
            }
        }
    }
    #pragma unroll
    for (int o = 16; o > 0; o >>= 1) acc += __shfl_down_sync(FULLMASK, acc, o);
    int warp = threadIdx.x >> 5, lane = threadIdx.x & 31;
    if (lane == 0) s_red[warp] = acc;
    __syncthreads();
    if (threadIdx.x == 0) {
        float t = 0.f;
        #pragma unroll
        for (int w = 0; w < 8; w++) t += s_red[w];
        atomicAdd(&g_lagg[b], t);
    }
}

// ---------------- kernel 3: bg selection + pairs + reg + combine + output ----------------
__global__ void __launch_bounds__(128) k_final(const float* __restrict__ emb,
                                               int HW, float invB, float* out)
{
    int b = blockIdx.x;
    int tid = threadIdx.x, lane = tid & 31, warp = tid >> 5;
    __shared__ float4 s_mean[KLBL];
    __shared__ int s_bg[100];
    __shared__ int s_cnt;
    __shared__ int s_wc[4];
    __shared__ float s_red[4];

    if (tid < KLBL) {
        int k = tid;
        float inv = 1.f / fmaxf(g_cntk[b][k], 1.f);
        float4 m;
        m.x = g_sum[b][k][0] * inv; m.y = g_sum[b][k][1] * inv;
        m.z = g_sum[b][k][2] * inv; m.w = g_sum[b][k][3] * inv;
        if (k == 0) { m.x = m.y = m.z = m.w = 0.f; }
        s_mean[k] = m;
    }
    if (tid == 0) s_cnt = 0;
    __syncthreads();

    const unsigned char* lab = g_lab + (size_t)b * HW;

    // ordered scan for first 100 background (label==0) pixels; HW % 128 == 0
    for (int pass = 0; pass < 2; pass++) {
        if (pass == 1 && s_cnt >= 100) break;  // fg-fill fallback rarely needed
        for (int base = 0; base < HW; base += 128) {
            int p = base + tid;
            bool f = (pass == 0) ? (lab[p] == 0) : (lab[p] != 0);
            unsigned bal = __ballot_sync(FULLMASK, f);
            if (lane == 0) s_wc[warp] = __popc(bal);
            __syncthreads();
            int before = s_cnt;
            int woff = 0;
            #pragma unroll
            for (int w = 0; w < 4; w++) if (w < warp) woff += s_wc[w];
            int total = s_wc[0] + s_wc[1] + s_wc[2] + s_wc[3];
            int rank = before + woff + __popc(bal & ((1u << lane) - 1u));
            if (f && rank < 100) s_bg[rank] = p;
            __syncthreads();
            if (tid == 0) s_cnt = before + total;
            __syncthreads();
            if (s_cnt >= 100) break;
        }
    }
    __syncthreads();

    const float coef = 1.0f - expf(-10.0f / 32.0f);

    // background term: 100 pixels x 31 means
    float acc_bg = 0.f;
    if (tid < 100) {
        int p = s_bg[tid];
        const float* eb = emb + (size_t)b * 4 * HW;
        float x0 = eb[p];
        float x1 = eb[(size_t)HW + p];
        float x2 = eb[2 * (size_t)HW + p];
        float x3 = eb[3 * (size_t)HW + p];
        #pragma unroll
        for (int k = 1; k < KLBL; k++) {
            float4 m = s_mean[k];
            float dx = x0 - m.x, dy = x1 - m.y, dz = x2 - m.z, dw = x3 - m.w;
            float dist = sqrtf(dx * dx + dy * dy + dz * dz + dw * dw);
            float y = fmaxf(fmaf(-coef, dist, TWO_DELTA_D), 0.f);
            acc_bg += logf(fmaf(y, y, 1.f));
        }
    }

    // pairwise term over labels 1..31, i != j
    float acc_pair = 0.f;
    for (int t = tid; t < 961; t += 128) {
        int i = t / 31 + 1, j = t % 31 + 1;
        if (i != j) {
            float4 mi = s_mean[i], mj = s_mean[j];
            float dx = mi.x - mj.x, dy = mi.y - mj.y;
            float dz = mi.z - mj.z, dw = mi.w - mj.w;
            float dist = sqrtf(dx * dx + dy * dy + dz * dz + dw * dw);
            float y = fmaxf(fmaf(-coef, dist, TWO_DELTA_D), 0.f);
            acc_pair += logf(fmaf(y, y, 1.f));
        }
    }

    // regularizer over all 32 labels (label 0 mean is 0 -> log(1)=0)
    float acc_reg = 0.f;
    if (tid < KLBL) {
        float4 m = s_mean[tid];
        float n = sqrtf(m.x * m.x + m.y * m.y + m.z * m.z + m.w * m.w);
        acc_reg = logf(n + 1.f);
    }

    float contrib = acc_pair * (1.f / 961.f)
                  + acc_bg * (1.f / (100.f * 961.f))
                  + acc_reg * (0.001f / 32.f);

    #pragma unroll
    for (int o = 16; o > 0; o >>= 1) contrib += __shfl_down_sync(FULLMASK, contrib, o);
    if (lane == 0) s_red[warp] = contrib;
    __syncthreads();
    if (tid == 0) {
        float t = s_red[0] + s_red[1] + s_red[2] + s_red[3];
        atomicAdd(out, (g_lagg[b] + t) * invB);
    }
}

// ---------------- launch ----------------
extern "C" void kernel_launch(void* const* d_in, const int* in_sizes, int n_in,
                              void* d_out, int out_size) {
    const float* emb  = (const float*)d_in[0];
    const int*   inst = (const int*)d_in[1];
    const float* ker  = (const float*)d_in[2];
    const float* tm   = (const float*)d_in[3];
    // d_in[4] = bboxes (unused by the loss)
    const float* maxd = (const float*)d_in[5];

    int B  = in_sizes[5] / KLBL;
    if (B < 1) B = 1;
    if (B > MAXB) B = MAXB;
    int HW = in_sizes[1] / B;
    int nv8 = HW >> 3;
    int nvec = HW >> 2;

    float* out = (float*)d_out;
    k_zero<<<(B * KLBL * 4 + 255) / 256, 256>>>(B, out);
    dim3 g1(74, B);   // 74*16 = 1184 = 148 SMs * 8 blocks -> single full wave
    k_pass1<<<g1, 256>>>(emb, inst, ker, tm, HW, nv8);
    k_pass2<<<g1, 256>>>(emb, maxd, HW, nvec);
    k_final<<<B, 128>>>(emb, HW, 1.f / (float)B, out);
}

// round 6
// speedup vs baseline: 6.1123x; 6.1123x over previous
#include <cuda_runtime.h>
#include <math.h>

#define KLBL 32
#define MAXB 16
#define MAXHW 409600
#define FULLMASK 0xffffffffu
#define DELTA_V 0.5f
#define TWO_DELTA_D 3.0f
#define CHUNK 12288   // k_final smem label-stage size (bytes)

// ---------------- scratch (device globals: no allocation allowed) ----------------
__device__ float g_sum[MAXB][KLBL][4];    // kernel-region segment sums
__device__ float g_cnt[MAXB][KLBL];       // per-label pixel count (tm-applied)
__device__ float g_cntk[MAXB][KLBL];      // per-label kernel-region count
__device__ float g_lagg[MAXB];            // accumulated l_agg per batch
__device__ unsigned char g_lab[(size_t)MAXB * MAXHW];  // tm-applied labels (6.5MB)

// ---------------- helpers ----------------
__device__ __forceinline__ float sqrt_approx(float x) {
    float r;
    asm("sqrt.approx.f32 %0, %1;" : "=f"(r) : "f"(x));
    return r;
}

// ---------------- kernel 0: zero accumulators + output ----------------
__global__ void k_zero(int B, float* out) {
    int t = blockIdx.x * blockDim.x + threadIdx.x;
    int n1 = B * KLBL;
    if (t < n1 * 4) ((float*)g_sum)[t] = 0.f;
    if (t < n1) { ((float*)g_cnt)[t] = 0.f; ((float*)g_cntk)[t] = 0.f; }
    if (t < B) g_lagg[t] = 0.f;
    if (t == 0) out[0] = 0.f;
}

// ---------------- kernel 1: segment sums / counts / label bytes ----------------
// Scatter into 32 bins via match_any + shuffle subset-sum (iterations = max
// group size ~4-5); group leader does non-atomic RMW into warp-private smem
// bins (distinct labels -> distinct addresses -> race-free).
__global__ void __launch_bounds__(256) k_pass1(
    const float* __restrict__ emb, const int* __restrict__ inst,
    const float* __restrict__ ker, const float* __restrict__ tmk,
    int HW, int nvec)
{
    int b = blockIdx.y;
    const float4* e0 = (const float4*)(emb + ((size_t)b * 4 + 0) * HW);
    const float4* e1 = (const float4*)(emb + ((size_t)b * 4 + 1) * HW);
    const float4* e2 = (const float4*)(emb + ((size_t)b * 4 + 2) * HW);
    const float4* e3 = (const float4*)(emb + ((size_t)b * 4 + 3) * HW);
    const int4*   ip = (const int4*)(inst + (size_t)b * HW);
    const float4* kp = (const float4*)(ker + (size_t)b * HW);
    const float4* tp = (const float4*)(tmk + (size_t)b * HW);
    unsigned int* lp = (unsigned int*)(g_lab + (size_t)b * HW);

    __shared__ float s_bins[8][KLBL][7];   // per-warp bins: 4 sums, cnt, cntk (+pad)
    for (int i = threadIdx.x; i < 8 * KLBL * 7; i += blockDim.x)
        ((float*)s_bins)[i] = 0.f;
    __syncthreads();

    int warp = threadIdx.x >> 5, lane = threadIdx.x & 31;
    float (*mybins)[7] = s_bins[warp];

    // nvec and the grid stride are multiples of 32 -> warps stay uniform
    for (int v = blockIdx.x * blockDim.x + threadIdx.x; v < nvec;
         v += gridDim.x * blockDim.x) {
        int4   iv = __ldcs(ip + v);
        float4 kv = __ldcs(kp + v);
        float4 tv = __ldcs(tp + v);
        float4 a = __ldg(e0 + v), b4 = __ldg(e1 + v);
        float4 c = __ldg(e2 + v), d4 = __ldg(e3 + v);

        float p0[4] = {a.x, a.y, a.z, a.w};
        float p1[4] = {b4.x, b4.y, b4.z, b4.w};
        float p2[4] = {c.x, c.y, c.z, c.w};
        float p3[4] = {d4.x, d4.y, d4.z, d4.w};
        int   iv4[4] = {iv.x, iv.y, iv.z, iv.w};
        float kv4[4] = {kv.x, kv.y, kv.z, kv.w};
        float tv4[4] = {tv.x, tv.y, tv.z, tv.w};

        unsigned packed = 0u;
        #pragma unroll
        for (int j = 0; j < 4; j++) {
            int L = (tv4[j] > 0.5f) ? iv4[j] : 0;
            bool kf = (kv4[j] > 0.5f);
            packed |= ((unsigned)L & 0xffu) << (8 * j);

            unsigned m  = __match_any_sync(FULLMASK, L);
            unsigned kb = __ballot_sync(FULLMASK, kf);
            unsigned mk = (L > 0) ? (m & kb) : 0u;

            float s0 = 0.f, s1 = 0.f, s2 = 0.f, s3 = 0.f;
            unsigned ii = mk;
            while (__any_sync(FULLMASK, ii != 0u)) {
                int src = ii ? (__ffs(ii) - 1) : 0;
                float t0 = __shfl_sync(FULLMASK, p0[j], src);
                float t1 = __shfl_sync(FULLMASK, p1[j], src);
                float t2 = __shfl_sync(FULLMASK, p2[j], src);
                float t3 = __shfl_sync(FULLMASK, p3[j], src);
                if (ii) { s0 += t0; s1 += t1; s2 += t2; s3 += t3; ii &= ii - 1u; }
            }
            if (L > 0 && (__ffs(m) - 1) == lane) {
                float* bp = mybins[L];
                bp[0] += s0; bp[1] += s1; bp[2] += s2; bp[3] += s3;
                bp[4] += (float)__popc(m);
                bp[5] += (float)__popc(m & kb);
            }
        }
        lp[v] = packed;
    }
    __syncthreads();

    // cross-warp reduce + one global atomic per (label, component)
    for (int i = threadIdx.x; i < KLBL * 6; i += blockDim.x) {
        int k = i / 6, comp = i % 6;
        float s = 0.f;
        #pragma unroll
        for (int w = 0; w < 8; w++) s += s_bins[w][k][comp];
        if (s != 0.f) {
            if (comp < 4)      atomicAdd(&g_sum[b][k][comp], s);
            else if (comp == 4) atomicAdd(&g_cnt[b][k], s);
            else                atomicAdd(&g_cntk[b][k], s);
        }
    }
}

// ---------------- kernel 2: l_agg (means recomputed locally, weighted reduce) ----------------
__global__ void __launch_bounds__(256) k_pass2(
    const float* __restrict__ emb, const float* __restrict__ maxd,
    int HW, int nvec)
{
    int b = blockIdx.y;
    __shared__ float4 s_mean[KLBL];
    __shared__ float  s_sc[KLBL];
    __shared__ float  s_w[KLBL];
    __shared__ float  s_red[8];
    if (threadIdx.x < KLBL) {
        int k = threadIdx.x;
        float inv = 1.f / fmaxf(g_cntk[b][k], 1.f);
        float4 m;
        m.x = g_sum[b][k][0] * inv; m.y = g_sum[b][k][1] * inv;
        m.z = g_sum[b][k][2] * inv; m.w = g_sum[b][k][3] * inv;
        if (k == 0) { m.x = m.y = m.z = m.w = 0.f; }
        s_mean[k] = m;
        s_sc[k] = expf(maxd[b * KLBL + k]);
        s_w[k]  = 1.f / (31.f * fmaxf(g_cnt[b][k], 1.f));
    }
    __syncthreads();

    const float4* e0 = (const float4*)(emb + ((size_t)b * 4 + 0) * HW);
    const float4* e1 = (const float4*)(emb + ((size_t)b * 4 + 1) * HW);
    const float4* e2 = (const float4*)(emb + ((size_t)b * 4 + 2) * HW);
    const float4* e3 = (const float4*)(emb + ((size_t)b * 4 + 3) * HW);
    const unsigned int* lp = (const unsigned int*)(g_lab + (size_t)b * HW);

    float acc = 0.f;
    for (int v = blockIdx.x * blockDim.x + threadIdx.x; v < nvec;
         v += gridDim.x * blockDim.x) {
        unsigned lw = __ldg(lp + v);
        float4 a = __ldcs(e0 + v), b4 = __ldcs(e1 + v);
        float4 c = __ldcs(e2 + v), d4 = __ldcs(e3 + v);
        float p0[4] = {a.x, a.y, a.z, a.w};
        float p1[4] = {b4.x, b4.y, b4.z, b4.w};
        float p2[4] = {c.x, c.y, c.z, c.w};
        float p3[4] = {d4.x, d4.y, d4.z, d4.w};
        #pragma unroll
        for (int j = 0; j < 4; j++) {
            int L = (lw >> (8 * j)) & 0xff;
            if (L) {
                float4 m = s_mean[L];
                float dx = p0[j] - m.x, dy = p1[j] - m.y;
                float dz = p2[j] - m.z, dw = p3[j] - m.w;
                float d2 = fmaf(dx, dx, fmaf(dy, dy, fmaf(dz, dz, dw * dw)));
                float dist = sqrt_approx(d2);
                float y = fmaxf(fmaf(s_sc[L], dist, -DELTA_V), 0.f);
                acc = fmaf(__logf(fmaf(y, y, 1.f)), s_w[L], acc);
            }
        }
    }
    #pragma unroll
    for (int o = 16; o > 0; o >>= 1) acc += __shfl_down_sync(FULLMASK, acc, o);
    int warp = threadIdx.x >> 5, lane = threadIdx.x & 31;
    if (lane == 0) s_red[warp] = acc;
    __syncthreads();
    if (threadIdx.x == 0) {
        float t = 0.f;
        #pragma unroll
        for (int w = 0; w < 8; w++) t += s_red[w];
        atomicAdd(&g_lagg[b], t);
    }
}

// ---------------- kernel 3: bg selection + pairs + reg + combine + output ----------------
__global__ void __launch_bounds__(128) k_final(const float* __restrict__ emb,
                                               int HW, float invB, float* out)
{
    int b = blockIdx.x;
    int tid = threadIdx.x, lane = tid & 31, warp = tid >> 5;
    __shared__ float4 s_mean[KLBL];
    __shared__ unsigned char s_lbl[CHUNK];
    __shared__ int s_bg[100];
    __shared__ int s_cnt;
    __shared__ int s_wc[4];
    __shared__ float s_red[4];

    if (tid < KLBL) {
        int k = tid;
        float inv = 1.f / fmaxf(g_cntk[b][k], 1.f);
        float4 m;
        m.x = g_sum[b][k][0] * inv; m.y = g_sum[b][k][1] * inv;
        m.z = g_sum[b][k][2] * inv; m.w = g_sum[b][k][3] * inv;
        if (k == 0) { m.x = m.y = m.z = m.w = 0.f; }
        s_mean[k] = m;
    }
    if (tid == 0) s_cnt = 0;
    __syncthreads();

    const unsigned char* lab = g_lab + (size_t)b * HW;

    // first 100 background (label==0) pixels in flat order, via smem-staged
    // chunks + ballot scan (512 px per iteration). pass 1 = fg-fill fallback.
    for (int pass = 0; pass < 2 && s_cnt < 100; pass++) {
        for (int cb = 0; cb < HW && s_cnt < 100; cb += CHUNK) {
            // stage CHUNK label bytes into smem (96 B/thread, uint4 loads)
            const uint4* src = (const uint4*)(lab + cb);
            uint4* dst = (uint4*)s_lbl;
            #pragma unroll
            for (int i = 0; i < CHUNK / (128 * 16); i++)
                dst[tid + i * 128] = __ldg(src + tid + i * 128);
            __syncthreads();

            for (int base = 0; base < CHUNK && s_cnt < 100; base += 512) {
                uchar4 q = ((const uchar4*)(s_lbl + base))[tid];
                bool f0, f1, f2, f3;
                if (pass == 0) {
                    f0 = q.x == 0; f1 = q.y == 0; f2 = q.z == 0; f3 = q.w == 0;
                } else {
                    f0 = q.x != 0; f1 = q.y != 0; f2 = q.z != 0; f3 = q.w != 0;
                }
                int c = (int)f0 + (int)f1 + (int)f2 + (int)f3;
                // warp inclusive scan of c
                int pre = c;
                #pragma unroll
                for (int o = 1; o < 32; o <<= 1) {
                    int t = __shfl_up_sync(FULLMASK, pre, o);
                    if (lane >= o) pre += t;
                }
                if (lane == 31) s_wc[warp] = pre;
                __syncthreads();
                int woff = 0;
                #pragma unroll
                for (int w = 0; w < 4; w++) if (w < warp) woff += s_wc[w];
                int r = s_cnt + woff + pre - c;   // exclusive rank
                int p = cb + base + tid * 4;
                if (f0) { if (r < 100) s_bg[r] = p + 0; r++; }
                if (f1) { if (r < 100) s_bg[r] = p + 1; r++; }
                if (f2) { if (r < 100) s_bg[r] = p + 2; r++; }
                if (f3) { if (r < 100) s_bg[r] = p + 3; r++; }
                __syncthreads();
                if (tid == 0)
                    s_cnt += s_wc[0] + s_wc[1] + s_wc[2] + s_wc[3];
                __syncthreads();
            }
        }
    }
    __syncthreads();

    const float coef = 1.0f - expf(-10.0f / 32.0f);

    // background term: 100 pixels x 31 means
    float acc_bg = 0.f;
    if (tid < 100) {
        int p = s_bg[tid];
        const float* eb = emb + (size_t)b * 4 * HW;
        float x0 = eb[p];
        float x1 = eb[(size_t)HW + p];
        float x2 = eb[2 * (size_t)HW + p];
        float x3 = eb[3 * (size_t)HW + p];
        #pragma unroll
        for (int k = 1; k < KLBL; k++) {
            float4 m = s_mean[k];
            float dx = x0 - m.x, dy = x1 - m.y, dz = x2 - m.z, dw = x3 - m.w;
            float dist = sqrtf(dx * dx + dy * dy + dz * dz + dw * dw);
            float y = fmaxf(fmaf(-coef, dist, TWO_DELTA_D), 0.f);
            acc_bg += logf(fmaf(y, y, 1.f));
        }
    }

    // pairwise term over labels 1..31, i != j
    float acc_pair = 0.f;
    for (int t = tid; t < 961; t += 128) {
        int i = t / 31 + 1, j = t % 31 + 1;
        if (i != j) {
            float4 mi = s_mean[i], mj = s_mean[j];
            float dx = mi.x - mj.x, dy = mi.y - mj.y;
            float dz = mi.z - mj.z, dw = mi.w - mj.w;
            float dist = sqrtf(dx * dx + dy * dy + dz * dz + dw * dw);
            float y = fmaxf(fmaf(-coef, dist, TWO_DELTA_D), 0.f);
            acc_pair += logf(fmaf(y, y, 1.f));
        }
    }

    // regularizer over all 32 labels (label 0 mean is 0 -> log(1)=0)
    float acc_reg = 0.f;
    if (tid < KLBL) {
        float4 m = s_mean[tid];
        float n = sqrtf(m.x * m.x + m.y * m.y + m.z * m.z + m.w * m.w);
        acc_reg = logf(n + 1.f);
    }

    float contrib = acc_pair * (1.f / 961.f)
                  + acc_bg * (1.f / (100.f * 961.f))
                  + acc_reg * (0.001f / 32.f);

    #pragma unroll
    for (int o = 16; o > 0; o >>= 1) contrib += __shfl_down_sync(FULLMASK, contrib, o);
    if (lane == 0) s_red[warp] = contrib;
    __syncthreads();
    if (tid == 0) {
        float t = s_red[0] + s_red[1] + s_red[2] + s_red[3];
        atomicAdd(out, (g_lagg[b] + t) * invB);
    }
}

// ---------------- launch ----------------
extern "C" void kernel_launch(void* const* d_in, const int* in_sizes, int n_in,
                              void* d_out, int out_size) {
    const float* emb  = (const float*)d_in[0];
    const int*   inst = (const int*)d_in[1];
    const float* ker  = (const float*)d_in[2];
    const float* tm   = (const float*)d_in[3];
    // d_in[4] = bboxes (unused by the loss)
    const float* maxd = (const float*)d_in[5];

    int B  = in_sizes[5] / KLBL;
    if (B < 1) B = 1;
    if (B > MAXB) B = MAXB;
    int HW = in_sizes[1] / B;
    int nvec = HW >> 2;

    float* out = (float*)d_out;
    k_zero<<<(B * KLBL * 4 + 255) / 256, 256>>>(B, out);
    dim3 g1(74, B);   // 74*16 = 1184 = 148 SMs * 8 blocks -> single full wave
    k_pass1<<<g1, 256>>>(emb, inst, ker, tm, HW, nvec);
    k_pass2<<<g1, 256>>>(emb, maxd, HW, nvec);
    k_final<<<B, 128>>>(emb, HW, 1.f / (float)B, out);
}

// round 8
// speedup vs baseline: 6.2508x; 1.0227x over previous
#include <cuda_runtime.h>
#include <math.h>

#define KLBL 32
#define MAXB 16
#define MAXHW 409600
#define FULLMASK 0xffffffffu
#define DELTA_V 0.5f
#define TWO_DELTA_D 3.0f
#define CHUNK 12288   // epilogue smem label-stage size (bytes, mult of 4096)

// ---------------- scratch (device globals: no allocation allowed) ----------------
__device__ float g_sum[MAXB][KLBL][4];    // kernel-region segment sums
__device__ float g_cnt[MAXB][KLBL];       // per-label pixel count (tm-applied)
__device__ float g_cntk[MAXB][KLBL];      // per-label kernel-region count
__device__ float g_lagg[MAXB];            // accumulated l_agg per batch
__device__ int   g_arrive[MAXB];          // pass2 per-batch completion counter
__device__ unsigned char g_lab[(size_t)MAXB * MAXHW];  // tm-applied labels (6.5MB)

// ---------------- helpers ----------------
__device__ __forceinline__ float sqrt_approx(float x) {
    float r;
    asm("sqrt.approx.f32 %0, %1;" : "=f"(r) : "f"(x));
    return r;
}

// ---------------- kernel 0: zero accumulators + output ----------------
__global__ void k_zero(int B, float* out) {
    int t = blockIdx.x * blockDim.x + threadIdx.x;
    int n1 = B * KLBL;
    if (t < n1 * 4) ((float*)g_sum)[t] = 0.f;
    if (t < n1) { ((float*)g_cnt)[t] = 0.f; ((float*)g_cntk)[t] = 0.f; }
    if (t < B) { g_lagg[t] = 0.f; g_arrive[t] = 0; }
    if (t == 0) out[0] = 0.f;
}

// ---------------- kernel 1: segment sums / counts / label bytes ----------------
// Scatter into 32 bins via match_any + shuffle subset-sum (iterations = max
// group size ~4-5); group leader does non-atomic RMW into warp-private smem
// bins (distinct labels -> distinct addresses -> race-free).
__global__ void __launch_bounds__(256) k_pass1(
    const float* __restrict__ emb, const int* __restrict__ inst,
    const float* __restrict__ ker, const float* __restrict__ tmk,
    int HW, int nvec)
{
    int b = blockIdx.y;
    const float4* e0 = (const float4*)(emb + ((size_t)b * 4 + 0) * HW);
    const float4* e1 = (const float4*)(emb + ((size_t)b * 4 + 1) * HW);
    const float4* e2 = (const float4*)(emb + ((size_t)b * 4 + 2) * HW);
    const float4* e3 = (const float4*)(emb + ((size_t)b * 4 + 3) * HW);
    const int4*   ip = (const int4*)(inst + (size_t)b * HW);
    const float4* kp = (const float4*)(ker + (size_t)b * HW);
    const float4* tp = (const float4*)(tmk + (size_t)b * HW);
    unsigned int* lp = (unsigned int*)(g_lab + (size_t)b * HW);

    __shared__ float s_bins[8][KLBL][7];   // per-warp bins: 4 sums, cnt, cntk (+pad)
    for (int i = threadIdx.x; i < 8 * KLBL * 7; i += blockDim.x)
        ((float*)s_bins)[i] = 0.f;
    __syncthreads();

    int warp = threadIdx.x >> 5, lane = threadIdx.x & 31;
    float (*mybins)[7] = s_bins[warp];

    for (int v = blockIdx.x * blockDim.x + threadIdx.x; v < nvec;
         v += gridDim.x * blockDim.x) {
        int4   iv = __ldcs(ip + v);
        float4 kv = __ldcs(kp + v);
        float4 tv = __ldcs(tp + v);
        float4 a = __ldg(e0 + v), b4 = __ldg(e1 + v);
        float4 c = __ldg(e2 + v), d4 = __ldg(e3 + v);

        float p0[4] = {a.x, a.y, a.z, a.w};
        float p1[4] = {b4.x, b4.y, b4.z, b4.w};
        float p2[4] = {c.x, c.y, c.z, c.w};
        float p3[4] = {d4.x, d4.y, d4.z, d4.w};
        int   iv4[4] = {iv.x, iv.y, iv.z, iv.w};
        float kv4[4] = {kv.x, kv.y, kv.z, kv.w};
        float tv4[4] = {tv.x, tv.y, tv.z, tv.w};

        unsigned packed = 0u;
        #pragma unroll
        for (int j = 0; j < 4; j++) {
            int L = (tv4[j] > 0.5f) ? iv4[j] : 0;
            bool kf = (kv4[j] > 0.5f);
            packed |= ((unsigned)L & 0xffu) << (8 * j);

            unsigned m  = __match_any_sync(FULLMASK, L);
            unsigned kb = __ballot_sync(FULLMASK, kf);
            unsigned mk = (L > 0) ? (m & kb) : 0u;

            float s0 = 0.f, s1 = 0.f, s2 = 0.f, s3 = 0.f;
            unsigned ii = mk;
            while (__any_sync(FULLMASK, ii != 0u)) {
                int src = ii ? (__ffs(ii) - 1) : 0;
                float t0 = __shfl_sync(FULLMASK, p0[j], src);
                float t1 = __shfl_sync(FULLMASK, p1[j], src);
                float t2 = __shfl_sync(FULLMASK, p2[j], src);
                float t3 = __shfl_sync(FULLMASK, p3[j], src);
                if (ii) { s0 += t0; s1 += t1; s2 += t2; s3 += t3; ii &= ii - 1u; }
            }
            if (L > 0 && (__ffs(m) - 1) == lane) {
                float* bp = mybins[L];
                bp[0] += s0; bp[1] += s1; bp[2] += s2; bp[3] += s3;
                bp[4] += (float)__popc(m);
                bp[5] += (float)__popc(m & kb);
            }
        }
        lp[v] = packed;
    }
    __syncthreads();

    for (int i = threadIdx.x; i < KLBL * 6; i += blockDim.x) {
        int k = i / 6, comp = i % 6;
        float s = 0.f;
        #pragma unroll
        for (int w = 0; w < 8; w++) s += s_bins[w][k][comp];
        if (s != 0.f) {
            if (comp < 4)      atomicAdd(&g_sum[b][k][comp], s);
            else if (comp == 4) atomicAdd(&g_cnt[b][k], s);
            else                atomicAdd(&g_cntk[b][k], s);
        }
    }
}

// ---------------- kernel 2: l_agg + fused per-batch epilogue ----------------
__global__ void __launch_bounds__(256) k_pass2(
    const float* __restrict__ emb, const float* __restrict__ maxd,
    int HW, int nvec, float invB, float* __restrict__ out)
{
    int b = blockIdx.y;
    int tid = threadIdx.x, warp = tid >> 5, lane = tid & 31;
    __shared__ float4 s_mean[KLBL];
    __shared__ float  s_sc[KLBL];
    __shared__ float  s_w[KLBL];
    __shared__ float  s_red[8];
    __shared__ int    s_last;
    if (tid < KLBL) {
        int k = tid;
        float inv = 1.f / fmaxf(g_cntk[b][k], 1.f);
        float4 m;
        m.x = g_sum[b][k][0] * inv; m.y = g_sum[b][k][1] * inv;
        m.z = g_sum[b][k][2] * inv; m.w = g_sum[b][k][3] * inv;
        if (k == 0) { m.x = m.y = m.z = m.w = 0.f; }
        s_mean[k] = m;
        s_sc[k] = expf(maxd[b * KLBL + k]);
        s_w[k]  = 1.f / (31.f * fmaxf(g_cnt[b][k], 1.f));
    }
    __syncthreads();

    const float4* e0 = (const float4*)(emb + ((size_t)b * 4 + 0) * HW);
    const float4* e1 = (const float4*)(emb + ((size_t)b * 4 + 1) * HW);
    const float4* e2 = (const float4*)(emb + ((size_t)b * 4 + 2) * HW);
    const float4* e3 = (const float4*)(emb + ((size_t)b * 4 + 3) * HW);
    const unsigned int* lp = (const unsigned int*)(g_lab + (size_t)b * HW);

    float acc = 0.f;
    for (int v = blockIdx.x * blockDim.x + tid; v < nvec;
         v += gridDim.x * blockDim.x) {
        unsigned lw = __ldg(lp + v);
        float4 a = __ldcs(e0 + v), b4 = __ldcs(e1 + v);
        float4 c = __ldcs(e2 + v), d4 = __ldcs(e3 + v);
        float p0[4] = {a.x, a.y, a.z, a.w};
        float p1[4] = {b4.x, b4.y, b4.z, b4.w};
        float p2[4] = {c.x, c.y, c.z, c.w};
        float p3[4] = {d4.x, d4.y, d4.z, d4.w};
        #pragma unroll
        for (int j = 0; j < 4; j++) {
            int L = (lw >> (8 * j)) & 0xff;
            if (L) {
                float4 m = s_mean[L];
                float dx = p0[j] - m.x, dy = p1[j] - m.y;
                float dz = p2[j] - m.z, dw = p3[j] - m.w;
                float d2 = fmaf(dx, dx, fmaf(dy, dy, fmaf(dz, dz, dw * dw)));
                float dist = sqrt_approx(d2);
                float y = fmaxf(fmaf(s_sc[L], dist, -DELTA_V), 0.f);
                acc = fmaf(__logf(fmaf(y, y, 1.f)), s_w[L], acc);
            }
        }
    }
    #pragma unroll
    for (int o = 16; o > 0; o >>= 1) acc += __shfl_down_sync(FULLMASK, acc, o);
    if (lane == 0) s_red[warp] = acc;
    __syncthreads();
    if (tid == 0) {
        float t = 0.f;
        #pragma unroll
        for (int w = 0; w < 8; w++) t += s_red[w];
        atomicAdd(&g_lagg[b], t);
        __threadfence();
        int prev = atomicAdd(&g_arrive[b], 1);
        s_last = (prev == gridDim.x - 1) ? 1 : 0;
    }
    __syncthreads();
    if (!s_last) return;

    // ======== epilogue: last block of batch b (g_lagg[b] is complete) ========
    __shared__ uint4 s_lbl4[CHUNK / 16];   // uint4 -> guaranteed 16B alignment
    unsigned char* s_lbl = (unsigned char*)s_lbl4;
    __shared__ int s_bg[100];
    __shared__ int s_cnt;
    __shared__ int s_wc[8];

    if (tid == 0) s_cnt = 0;
    __syncthreads();

    const unsigned char* lab = g_lab + (size_t)b * HW;

    // first 100 background (label==0) pixels in flat order; staged chunks,
    // 1024 px per ballot-scan iteration. pass 1 = fg-fill fallback.
    for (int pass = 0; pass < 2 && s_cnt < 100; pass++) {
        for (int cb = 0; cb < HW && s_cnt < 100; cb += CHUNK) {
            const uint4* src = (const uint4*)(lab + cb);
            #pragma unroll
            for (int i = 0; i < CHUNK / (256 * 16); i++)
                s_lbl4[tid + i * 256] = __ldg(src + tid + i * 256);
            __syncthreads();

            for (int base = 0; base < CHUNK && s_cnt < 100; base += 1024) {
                uchar4 q = ((const uchar4*)(s_lbl + base))[tid];
                bool f0, f1, f2, f3;
                if (pass == 0) {
                    f0 = q.x == 0; f1 = q.y == 0; f2 = q.z == 0; f3 = q.w == 0;
                } else {
                    f0 = q.x != 0; f1 = q.y != 0; f2 = q.z != 0; f3 = q.w != 0;
                }
                int c = (int)f0 + (int)f1 + (int)f2 + (int)f3;
                int pre = c;
                #pragma unroll
                for (int o = 1; o < 32; o <<= 1) {
                    int t = __shfl_up_sync(FULLMASK, pre, o);
                    if (lane >= o) pre += t;
                }
                if (lane == 31) s_wc[warp] = pre;
                __syncthreads();
                int woff = 0;
                #pragma unroll
                for (int w = 0; w < 8; w++) if (w < warp) woff += s_wc[w];
                int r = s_cnt + woff + pre - c;   // exclusive rank
                int p = cb + base + tid * 4;
                if (f0) { if (r < 100) s_bg[r] = p + 0; r++; }
                if (f1) { if (r < 100) s_bg[r] = p + 1; r++; }
                if (f2) { if (r < 100) s_bg[r] = p + 2; r++; }
                if (f3) { if (r < 100) s_bg[r] = p + 3; r++; }
                __syncthreads();
                if (tid == 0) {
                    int tot = 0;
                    #pragma unroll
                    for (int w = 0; w < 8; w++) tot += s_wc[w];
                    s_cnt += tot;
                }
                __syncthreads();
            }
        }
    }
    __syncthreads();

    const float coef = 1.0f - expf(-10.0f / 32.0f);

    // background term: 100 pixels x 31 means
    float acc_bg = 0.f;
    if (tid < 100) {
        int p = s_bg[tid];
        const float* eb = emb + (size_t)b * 4 * HW;
        float x0 = eb[p];
        float x1 = eb[(size_t)HW + p];
        float x2 = eb[2 * (size_t)HW + p];
        float x3 = eb[3 * (size_t)HW + p];
        #pragma unroll
        for (int k = 1; k < KLBL; k++) {
            float4 m = s_mean[k];
            float dx = x0 - m.x, dy = x1 - m.y, dz = x2 - m.z, dw = x3 - m.w;
            float dist = sqrtf(dx * dx + dy * dy + dz * dz + dw * dw);
            float y = fmaxf(fmaf(-coef, dist, TWO_DELTA_D), 0.f);
            acc_bg += __logf(fmaf(y, y, 1.f));
        }
    }

    // pairwise term over labels 1..31, i != j
    float acc_pair = 0.f;
    for (int t = tid; t < 961; t += 256) {
        int i = t / 31 + 1, j = t % 31 + 1;
        if (i != j) {
            float4 mi = s_mean[i], mj = s_mean[j];
            float dx = mi.x - mj.x, dy = mi.y - mj.y;
            float dz = mi.z - mj.z, dw = mi.w - mj.w;
            float dist = sqrtf(dx * dx + dy * dy + dz * dz + dw * dw);
            float y = fmaxf(fmaf(-coef, dist, TWO_DELTA_D), 0.f);
            acc_pair += __logf(fmaf(y, y, 1.f));
        }
    }

    // regularizer over all 32 labels (label 0 mean is 0 -> log(1)=0)
    float acc_reg = 0.f;
    if (tid < KLBL) {
        float4 m = s_mean[tid];
        float n = sqrtf(m.x * m.x + m.y * m.y + m.z * m.z + m.w * m.w);
        acc_reg = logf(n + 1.f);
    }

    float contrib = acc_pair * (1.f / 961.f)
                  + acc_bg * (1.f / (100.f * 961.f))
                  + acc_reg * (0.001f / 32.f);

    #pragma unroll
    for (int o = 16; o > 0; o >>= 1) contrib += __shfl_down_sync(FULLMASK, contrib, o);
    if (lane == 0) s_red[warp] = contrib;
    __syncthreads();
    if (tid == 0) {
        float t = 0.f;
        #pragma unroll
        for (int w = 0; w < 8; w++) t += s_red[w];
        atomicAdd(out, (g_lagg[b] + t) * invB);
    }
}

// ---------------- launch ----------------
extern "C" void kernel_launch(void* const* d_in, const int* in_sizes, int n_in,
                              void* d_out, int out_size) {
    const float* emb  = (const float*)d_in[0];
    const int*   inst = (const int*)d_in[1];
    const float* ker  = (const float*)d_in[2];
    const float* tm   = (const float*)d_in[3];
    // d_in[4] = bboxes (unused by the loss)
    const float* maxd = (const float*)d_in[5];

    int B  = in_sizes[5] / KLBL;
    if (B < 1) B = 1;
    if (B > MAXB) B = MAXB;
    int HW = in_sizes[1] / B;
    int nvec = HW >> 2;

    float* out = (float*)d_out;
    k_zero<<<(B * KLBL * 4 + 255) / 256, 256>>>(B, out);
    dim3 g1(74, B);   // 74*16 = 1184 blocks
    k_pass1<<<g1, 256>>>(emb, inst, ker, tm, HW, nvec);
    k_pass2<<<g1, 256>>>(emb, maxd, HW, nvec, 1.f / (float)B, out);
}